// round 4
// baseline (speedup 1.0000x reference)
#include <cuda_runtime.h>
#include <math.h>

// Problem constants (fixed by the reference)
#define BB 8
#define NN 900
#define CC 256
#define HEADS 8
#define PP 4
#define HD 32
#define BH 200
#define BW 200
#define HW (BH*BW)
#define RADIUS 0.2f
#define QB 10                 // queries per block (kernel A)
#define NBLKA ((BB*NN)/QB)    // 720
#define QB2 32                // queries per block (kernel B)
#define NBLKB ((BB*NN)/QB2)   // 225
#define FS_STRIDE 34          // padded row stride (floats); 136B, 8B-aligned, odd/even bank spread

// Intermediate fused features [B*N][C]
__device__ float g_fused[BB*NN*CC];

// ---------------------------------------------------------------------------
// Kernel A: offset/weight GEMV + sampling setup + bilinear gather
// ---------------------------------------------------------------------------
__global__ __launch_bounds__(256, 6)
void deform_sample_kernel(
    const float* __restrict__ query,
    const float* __restrict__ memory,
    const float* __restrict__ refpts,
    const float* __restrict__ w_off,
    const float* __restrict__ b_off,
    const float* __restrict__ w_wt,
    const float* __restrict__ b_wt)
{
    __shared__ float q_s[QB][CC];        // 10 KB
    __shared__ float ow_s[QB][96];       // 3.75 KB
    __shared__ float sampw_s[QB][32][4]; // 5 KB
    __shared__ int   sampi_s[QB][32][4]; // 5 KB

    const int t = threadIdx.x;
    const int base = blockIdx.x * QB;    // all QB queries share one batch (900 % 10 == 0)
    const int b = base / NN;

    // ---- Phase 1: stage QB query rows ----
    #pragma unroll
    for (int i = t; i < QB*CC; i += 256) {
        int qq = i >> 8, k = i & 255;
        q_s[qq][k] = query[(size_t)(base + qq)*CC + k];
    }
    __syncthreads();

    // ---- Phase 2: offset+weight GEMV (96 cols x 10 queries, 2 groups) ----
    {
        int g = -1, tt = 0;
        if (t < 96)                    { g = 0; tt = t; }
        else if (t >= 128 && t < 224)  { g = 1; tt = t - 128; }
        if (g >= 0) {
            const int q0 = g * 5;
            const bool is_off = (tt < 64);
            const float* W = is_off ? w_off : w_wt;
            const int col  = is_off ? tt : (tt - 64);
            const int ldw  = is_off ? 64 : 32;
            float acc[5];
            const float bias = is_off ? b_off[col] : b_wt[col];
            #pragma unroll
            for (int qq = 0; qq < 5; qq++) acc[qq] = bias;

            for (int k4 = 0; k4 < CC; k4 += 4) {
                float w0 = W[(k4+0)*ldw + col];
                float w1 = W[(k4+1)*ldw + col];
                float w2 = W[(k4+2)*ldw + col];
                float w3 = W[(k4+3)*ldw + col];
                #pragma unroll
                for (int qq = 0; qq < 5; qq++) {
                    float4 qv = *(const float4*)&q_s[q0+qq][k4];
                    acc[qq] += qv.x*w0 + qv.y*w1 + qv.z*w2 + qv.w*w3;
                }
            }
            #pragma unroll
            for (int qq = 0; qq < 5; qq++) ow_s[q0+qq][tt] = acc[qq];
        }
    }
    __syncthreads();

    // ---- Phase 3: tanh offsets, softmax(P), bilinear setup ----
    {
        const int lane = t & 31;
        for (int qq = (t >> 5); qq < QB; qq += 8) {
            const int flat = base + qq;
            float rx = refpts[(size_t)flat*2 + 0];
            float ry = refpts[(size_t)flat*2 + 1];

            float ox = tanhf(ow_s[qq][2*lane    ]) * RADIUS;
            float oy = tanhf(ow_s[qq][2*lane + 1]) * RADIUS;
            float x = (rx + ox) * (float)BW - 0.5f;
            float y = (ry + oy) * (float)BH - 0.5f;
            float x0f = floorf(x), y0f = floorf(y);
            int   x0 = (int)x0f,   y0 = (int)y0f;
            float fx = x - x0f,    fy = y - y0f;

            float lg = ow_s[qq][64 + lane];
            float m = lg;
            m = fmaxf(m, __shfl_xor_sync(0xffffffffu, m, 1));
            m = fmaxf(m, __shfl_xor_sync(0xffffffffu, m, 2));
            float e = expf(lg - m);
            float s = e;
            s += __shfl_xor_sync(0xffffffffu, s, 1);
            s += __shfl_xor_sync(0xffffffffu, s, 2);
            float wt = e / s;

            #pragma unroll
            for (int c = 0; c < 4; c++) {
                int xi = x0 + (c & 1);
                int yi = y0 + (c >> 1);
                bool valid = (xi >= 0) & (xi < BW) & (yi >= 0) & (yi < BH);
                float bwx = (c & 1)  ? fx : (1.f - fx);
                float bwy = (c >> 1) ? fy : (1.f - fy);
                int xc = min(max(xi, 0), BW - 1);
                int yc = min(max(yi, 0), BH - 1);
                sampw_s[qq][lane][c] = valid ? (wt * bwx * bwy) : 0.f;
                sampi_s[qq][lane][c] = yc * BW + xc;
            }
        }
    }
    __syncthreads();

    // ---- Phase 4: branchless gather, MLP=8 batches ----
    // warp = one head (h = t>>5), lanes = hd dims -> coalesced 128B loads
    {
        const int h = t >> 5, d = t & 31;
        const float* mb = memory + (size_t)b * HW * CC + h * HD + d;
        #pragma unroll 1
        for (int qq = 0; qq < QB; qq++) {
            float acc = 0.f;
            #pragma unroll
            for (int half = 0; half < 2; half++) {
                float wv[8]; int ix[8];
                #pragma unroll
                for (int u = 0; u < 8; u++) {
                    int pc = half*8 + u;
                    int p = pc >> 2, c = pc & 3;
                    wv[u] = sampw_s[qq][h*4 + p][c];   // warp-uniform
                    ix[u] = sampi_s[qq][h*4 + p][c];   // warp-uniform
                }
                float v[8];
                #pragma unroll
                for (int u = 0; u < 8; u++) v[u] = mb[(size_t)ix[u]*CC];
                #pragma unroll
                for (int u = 0; u < 8; u++) acc += wv[u]*v[u];
            }
            g_fused[(size_t)(base + qq)*CC + h*HD + d] = acc;
        }
    }
}

// ---------------------------------------------------------------------------
// Kernel B: projection GEMM [7200,256] @ [256,256] with packed f32x2 FMA
// ---------------------------------------------------------------------------
__device__ __forceinline__ unsigned long long pk2(float x) {
    unsigned long long r;
    asm("mov.b64 %0, {%1, %1};" : "=l"(r) : "f"(x));
    return r;
}
__device__ __forceinline__ void ffma2(unsigned long long& acc,
                                      unsigned long long a,
                                      unsigned long long b) {
    asm("fma.rn.f32x2 %0, %1, %2, %0;" : "+l"(acc) : "l"(a), "l"(b));
}

__global__ __launch_bounds__(256, 3)
void deform_proj_kernel(
    const float* __restrict__ w_out,
    const float* __restrict__ b_out,
    float* __restrict__ out)
{
    // Transposed fused tile: fs[k][q], row stride 34 floats (136 B, 8B-aligned)
    __shared__ float fs[CC * FS_STRIDE];   // 34 KB

    const int t = threadIdx.x;             // output column
    const int base = blockIdx.x * QB2;

    // Load + transpose 32 query rows into smem
    #pragma unroll
    for (int i = t; i < QB2*CC; i += 256) {
        int q = i >> 8, k = i & 255;
        fs[k*FS_STRIDE + q] = g_fused[(size_t)(base + q)*CC + k];
    }
    __syncthreads();

    // 16 packed accumulators: acc[j] = (out[2j], out[2j+1]) for column t
    unsigned long long acc[16];
    #pragma unroll
    for (int j = 0; j < 16; j++) acc[j] = 0ull;

    #pragma unroll 1
    for (int k = 0; k < CC; k += 2) {
        float wa = w_out[(size_t)(k+0)*CC + t];
        float wb = w_out[(size_t)(k+1)*CC + t];
        unsigned long long wwa = pk2(wa);
        unsigned long long wwb = pk2(wb);
        const unsigned long long* rowa = (const unsigned long long*)(fs + (k+0)*FS_STRIDE);
        const unsigned long long* rowb = (const unsigned long long*)(fs + (k+1)*FS_STRIDE);
        #pragma unroll
        for (int j = 0; j < 16; j++) {
            unsigned long long ua = rowa[j];   // query pair (2j, 2j+1), warp-uniform broadcast
            ffma2(acc[j], ua, wwa);
        }
        #pragma unroll
        for (int j = 0; j < 16; j++) {
            unsigned long long ub = rowb[j];
            ffma2(acc[j], ub, wwb);
        }
    }

    const float bo = b_out[t];
    #pragma unroll
    for (int j = 0; j < 16; j++) {
        float lo, hi;
        asm("mov.b64 {%0, %1}, %2;" : "=f"(lo), "=f"(hi) : "l"(acc[j]));
        out[(size_t)(base + 2*j + 0)*CC + t] = lo + bo;
        out[(size_t)(base + 2*j + 1)*CC + t] = hi + bo;
    }
}

extern "C" void kernel_launch(void* const* d_in, const int* in_sizes, int n_in,
                              void* d_out, int out_size) {
    const float* query  = (const float*)d_in[0];
    const float* memory = (const float*)d_in[1];
    const float* refpts = (const float*)d_in[2];
    const float* w_off  = (const float*)d_in[3];
    const float* b_off  = (const float*)d_in[4];
    const float* w_wt   = (const float*)d_in[5];
    const float* b_wt   = (const float*)d_in[6];
    const float* w_out  = (const float*)d_in[7];
    const float* b_out  = (const float*)d_in[8];

    deform_sample_kernel<<<NBLKA, 256>>>(query, memory, refpts,
                                         w_off, b_off, w_wt, b_wt);
    deform_proj_kernel<<<NBLKB, 256>>>(w_out, b_out, (float*)d_out);
}

// round 5
// speedup vs baseline: 1.1201x; 1.1201x over previous
#include <cuda_runtime.h>
#include <math.h>

// Problem constants (fixed by the reference)
#define BB 8
#define NN 900
#define CC 256
#define HEADS 8
#define PP 4
#define HD 32
#define BH 200
#define BW 200
#define HW (BH*BW)
#define RADIUS 0.2f
#define QB 10                 // queries per block
#define NBLK ((BB*NN)/QB)     // 720 -> one wave at 5 blocks/SM on 148 SMs
#define TSTRIDE 14            // padded row stride (floats): even (8B-aligned pairs), 2-way conflict max

__device__ __forceinline__ unsigned long long pk2(float x) {
    unsigned long long r;
    asm("mov.b64 %0, {%1, %1};" : "=l"(r) : "f"(x));
    return r;
}
__device__ __forceinline__ void ffma2(unsigned long long& acc,
                                      unsigned long long a,
                                      unsigned long long b) {
    asm("fma.rn.f32x2 %0, %1, %2, %0;" : "+l"(acc) : "l"(a), "l"(b));
}
__device__ __forceinline__ void unpk2(unsigned long long v, float& lo, float& hi) {
    asm("mov.b64 {%0, %1}, %2;" : "=f"(lo), "=f"(hi) : "l"(v));
}

__global__ __launch_bounds__(256, 5)
void deform_fused_kernel(
    const float* __restrict__ query,
    const float* __restrict__ memory,
    const float* __restrict__ refpts,
    const float* __restrict__ w_off,
    const float* __restrict__ b_off,
    const float* __restrict__ w_wt,
    const float* __restrict__ b_wt,
    const float* __restrict__ w_out,
    const float* __restrict__ b_out,
    float* __restrict__ out)
{
    // Transposed union buffer: phases 1-2 hold queryT[k][q]; phases 4-5 hold fusedT[k][q]
    __shared__ float bufT[CC][TSTRIDE];     // 14.3 KB
    __shared__ float pow_s[2][96][QB];      // 7.5 KB : k-split partial logits
    __shared__ float sampw_s[QB][32][4];    // 5 KB
    __shared__ int   sampi_s[QB][32][4];    // 5 KB

    const int t = threadIdx.x;
    const int base = blockIdx.x * QB;       // all QB queries share one batch (900 % 10 == 0)
    const int b = base / NN;

    // ---- Phase 1: stage QB query rows, transposed ----
    #pragma unroll
    for (int i = t; i < QB*CC; i += 256) {
        int qq = i >> 8, k = i & 255;
        bufT[k][qq] = query[(size_t)(base + qq)*CC + k];
    }
    __syncthreads();

    // ---- Phase 2: offset+weight GEMV, k-split across two thread groups ----
    // group 0: threads 0..95  -> k in [0,128);  group 1: threads 128..223 -> k in [128,256)
    {
        int g = -1, tt = 0;
        if (t < 96)                    { g = 0; tt = t; }
        else if (t >= 128 && t < 224)  { g = 1; tt = t - 128; }
        if (g >= 0) {
            const bool is_off = (tt < 64);
            const float* W = is_off ? w_off : w_wt;
            const int col  = is_off ? tt : (tt - 64);
            const int ldw  = is_off ? 64 : 32;
            const int k0 = g * 128, k1 = k0 + 128;

            unsigned long long acc[5];
            #pragma unroll
            for (int j = 0; j < 5; j++) acc[j] = 0ull;

            #pragma unroll 4
            for (int k = k0; k < k1; k++) {
                unsigned long long ww = pk2(W[k*ldw + col]);
                const unsigned long long* row = (const unsigned long long*)&bufT[k][0];
                #pragma unroll
                for (int j = 0; j < 5; j++) ffma2(acc[j], row[j], ww);
            }
            #pragma unroll
            for (int j = 0; j < 5; j++) {
                float lo, hi; unpk2(acc[j], lo, hi);
                pow_s[g][tt][2*j+0] = lo;
                pow_s[g][tt][2*j+1] = hi;
            }
        }
    }
    __syncthreads();

    // ---- Phase 3: combine partials + bias, tanh offsets, softmax(P), setup ----
    {
        const int lane = t & 31;
        for (int qq = (t >> 5); qq < QB; qq += 8) {
            const int flat = base + qq;
            float rx = refpts[(size_t)flat*2 + 0];
            float ry = refpts[(size_t)flat*2 + 1];

            float lgx = pow_s[0][2*lane  ][qq] + pow_s[1][2*lane  ][qq] + b_off[2*lane  ];
            float lgy = pow_s[0][2*lane+1][qq] + pow_s[1][2*lane+1][qq] + b_off[2*lane+1];
            float ox = tanhf(lgx) * RADIUS;
            float oy = tanhf(lgy) * RADIUS;
            float x = (rx + ox) * (float)BW - 0.5f;
            float y = (ry + oy) * (float)BH - 0.5f;
            float x0f = floorf(x), y0f = floorf(y);
            int   x0 = (int)x0f,   y0 = (int)y0f;
            float fx = x - x0f,    fy = y - y0f;

            float lg = pow_s[0][64+lane][qq] + pow_s[1][64+lane][qq] + b_wt[lane];
            float m = lg;
            m = fmaxf(m, __shfl_xor_sync(0xffffffffu, m, 1));
            m = fmaxf(m, __shfl_xor_sync(0xffffffffu, m, 2));
            float e = expf(lg - m);
            float s = e;
            s += __shfl_xor_sync(0xffffffffu, s, 1);
            s += __shfl_xor_sync(0xffffffffu, s, 2);
            float wt = e / s;

            #pragma unroll
            for (int c = 0; c < 4; c++) {
                int xi = x0 + (c & 1);
                int yi = y0 + (c >> 1);
                bool valid = (xi >= 0) & (xi < BW) & (yi >= 0) & (yi < BH);
                float bwx = (c & 1)  ? fx : (1.f - fx);
                float bwy = (c >> 1) ? fy : (1.f - fy);
                int xc = min(max(xi, 0), BW - 1);
                int yc = min(max(yi, 0), BH - 1);
                sampw_s[qq][lane][c] = valid ? (wt * bwx * bwy) : 0.f;
                sampi_s[qq][lane][c] = yc * BW + xc;
            }
        }
    }
    __syncthreads();

    // ---- Phase 4: branchless gather, MLP=8 batches; write transposed ----
    // warp = one head (h = t>>5), lanes = hd dims -> coalesced 128B loads
    {
        const int h = t >> 5, d = t & 31;
        const float* mb = memory + (size_t)b * HW * CC + h * HD + d;
        #pragma unroll 1
        for (int qq = 0; qq < QB; qq++) {
            float acc = 0.f;
            #pragma unroll
            for (int half = 0; half < 2; half++) {
                float wv[8]; int ix[8];
                #pragma unroll
                for (int u = 0; u < 8; u++) {
                    int pc = half*8 + u;
                    int p = pc >> 2, c = pc & 3;
                    wv[u] = sampw_s[qq][h*4 + p][c];   // warp-uniform
                    ix[u] = sampi_s[qq][h*4 + p][c];   // warp-uniform
                }
                float v[8];
                #pragma unroll
                for (int u = 0; u < 8; u++) v[u] = mb[(size_t)ix[u]*CC];
                #pragma unroll
                for (int u = 0; u < 8; u++) acc += wv[u]*v[u];
            }
            bufT[h*HD + d][qq] = acc;                  // fusedT[k][q]
        }
    }
    __syncthreads();

    // ---- Phase 5: output projection [QBx256] @ [256x256], packed f32x2 ----
    {
        unsigned long long acc[5];
        #pragma unroll
        for (int j = 0; j < 5; j++) acc[j] = 0ull;

        #pragma unroll 4
        for (int k = 0; k < CC; k++) {
            unsigned long long ww = pk2(w_out[(size_t)k*CC + t]);
            const unsigned long long* row = (const unsigned long long*)&bufT[k][0];
            #pragma unroll
            for (int j = 0; j < 5; j++) ffma2(acc[j], row[j], ww);
        }

        const float bo = b_out[t];
        #pragma unroll
        for (int j = 0; j < 5; j++) {
            float lo, hi; unpk2(acc[j], lo, hi);
            out[(size_t)(base + 2*j + 0)*CC + t] = lo + bo;
            out[(size_t)(base + 2*j + 1)*CC + t] = hi + bo;
        }
    }
}

extern "C" void kernel_launch(void* const* d_in, const int* in_sizes, int n_in,
                              void* d_out, int out_size) {
    const float* query  = (const float*)d_in[0];
    const float* memory = (const float*)d_in[1];
    const float* refpts = (const float*)d_in[2];
    const float* w_off  = (const float*)d_in[3];
    const float* b_off  = (const float*)d_in[4];
    const float* w_wt   = (const float*)d_in[5];
    const float* b_wt   = (const float*)d_in[6];
    const float* w_out  = (const float*)d_in[7];
    const float* b_out  = (const float*)d_in[8];

    deform_fused_kernel<<<NBLK, 256>>>(query, memory, refpts,
                                       w_off, b_off, w_wt, b_wt,
                                       w_out, b_out, (float*)d_out);
}

// round 8
// speedup vs baseline: 1.3787x; 1.2309x over previous
#include <cuda_runtime.h>
#include <math.h>

// Problem constants (fixed by the reference)
#define BB 8
#define NN 900
#define CC 256
#define HEADS 8
#define PP 4
#define HD 32
#define BH 200
#define BW 200
#define HW (BH*BW)
#define RADIUS 0.2f
#define QB 16                 // queries per block
#define NBLK ((BB*NN)/QB)     // 450 -> one wave at 4 blocks/SM on 148 SMs
#define TSTRIDE 18            // padded row stride (floats): 72B, 8B-aligned pairs

__device__ __forceinline__ unsigned long long pk2(float x) {
    unsigned long long r;
    asm("mov.b64 %0, {%1, %1};" : "=l"(r) : "f"(x));
    return r;
}
__device__ __forceinline__ void ffma2(unsigned long long& acc,
                                      unsigned long long a,
                                      unsigned long long b) {
    asm("fma.rn.f32x2 %0, %1, %2, %0;" : "+l"(acc) : "l"(a), "l"(b));
}
__device__ __forceinline__ void unpk2(unsigned long long v, float& lo, float& hi) {
    asm("mov.b64 {%0, %1}, %2;" : "=f"(lo), "=f"(hi) : "l"(v));
}

__global__ __launch_bounds__(256, 4)
void deform_fused_kernel(
    const float* __restrict__ query,
    const float* __restrict__ memory,
    const float* __restrict__ refpts,
    const float* __restrict__ w_off,
    const float* __restrict__ b_off,
    const float* __restrict__ w_wt,
    const float* __restrict__ b_wt,
    const float* __restrict__ w_out,
    const float* __restrict__ b_out,
    float* __restrict__ out)
{
    // Transposed union buffer: phases 1-2 hold queryT[k][q]; phases 4-5 hold fusedT[k][q]
    __shared__ float bufT[CC][TSTRIDE];          // 18 KB
    __shared__ float pow_s[2][96][QB];           // 12 KB : k-split partial logits
    __shared__ float sampw_s[QB][HEADS*PP][4];   // 8 KB  (rows 16B-aligned)
    __shared__ int   sampi_s[QB][HEADS*PP][4];   // 8 KB
    // total 46 KB/block * 4 blocks = 184 KB/SM

    const int t = threadIdx.x;
    const int base = blockIdx.x * QB;

    // ---- Phase 1: stage QB query rows, transposed (k = t) ----
    #pragma unroll 4
    for (int j = 0; j < QB; j++)
        bufT[t][j] = query[(size_t)(base + j)*CC + t];
    __syncthreads();

    // ---- Phase 2: offset+weight GEMV, k-split, prefetched, packed ----
    // group 0: threads 0..95  -> k in [0,128);  group 1: threads 128..223 -> k in [128,256)
    {
        int g = -1, tt = 0;
        if (t < 96)                    { g = 0; tt = t; }
        else if (t >= 128 && t < 224)  { g = 1; tt = t - 128; }
        if (g >= 0) {
            const bool is_off = (tt < 64);
            const float* W = is_off ? w_off : w_wt;
            const int col  = is_off ? tt : (tt - 64);
            const int ldw  = is_off ? 64 : 32;
            const int k0   = g * 128;

            unsigned long long acc[8];
            #pragma unroll
            for (int u = 0; u < 8; u++) acc[u] = 0ull;

            float wc[4], wn[4];
            #pragma unroll
            for (int j = 0; j < 4; j++) wc[j] = W[(k0 + j)*ldw + col];

            #pragma unroll 1
            for (int kb = 0; kb < 128; kb += 4) {
                const bool more = (kb + 4) < 128;
                #pragma unroll
                for (int j = 0; j < 4; j++)
                    wn[j] = more ? W[(k0 + kb + 4 + j)*ldw + col] : 0.f;
                #pragma unroll
                for (int j = 0; j < 4; j++) {
                    unsigned long long ww = pk2(wc[j]);
                    const unsigned long long* row =
                        (const unsigned long long*)&bufT[k0 + kb + j][0];
                    #pragma unroll
                    for (int u = 0; u < 8; u++) ffma2(acc[u], row[u], ww);
                }
                #pragma unroll
                for (int j = 0; j < 4; j++) wc[j] = wn[j];
            }
            #pragma unroll
            for (int u = 0; u < 8; u++) {
                float lo, hi; unpk2(acc[u], lo, hi);
                pow_s[g][tt][2*u+0] = lo;
                pow_s[g][tt][2*u+1] = hi;
            }
        }
    }
    __syncthreads();

    // ---- Phase 3: combine partials + bias, tanh, softmax(P), bilinear setup ----
    {
        const int lane = t & 31;
        for (int qq = (t >> 5); qq < QB; qq += 8) {
            const int flat = base + qq;
            float rx = refpts[(size_t)flat*2 + 0];
            float ry = refpts[(size_t)flat*2 + 1];

            float lgx = pow_s[0][2*lane  ][qq] + pow_s[1][2*lane  ][qq] + b_off[2*lane  ];
            float lgy = pow_s[0][2*lane+1][qq] + pow_s[1][2*lane+1][qq] + b_off[2*lane+1];
            float ox = tanhf(lgx) * RADIUS;
            float oy = tanhf(lgy) * RADIUS;
            float x = (rx + ox) * (float)BW - 0.5f;
            float y = (ry + oy) * (float)BH - 0.5f;
            float x0f = floorf(x), y0f = floorf(y);
            int   x0 = (int)x0f,   y0 = (int)y0f;
            float fx = x - x0f,    fy = y - y0f;

            float lg = pow_s[0][64+lane][qq] + pow_s[1][64+lane][qq] + b_wt[lane];
            float m = lg;
            m = fmaxf(m, __shfl_xor_sync(0xffffffffu, m, 1));
            m = fmaxf(m, __shfl_xor_sync(0xffffffffu, m, 2));
            float e = expf(lg - m);
            float s = e;
            s += __shfl_xor_sync(0xffffffffu, s, 1);
            s += __shfl_xor_sync(0xffffffffu, s, 2);
            float wt = e / s;

            #pragma unroll
            for (int c = 0; c < 4; c++) {
                int xi = x0 + (c & 1);
                int yi = y0 + (c >> 1);
                bool valid = (xi >= 0) & (xi < BW) & (yi >= 0) & (yi < BH);
                float bwx = (c & 1)  ? fx : (1.f - fx);
                float bwy = (c >> 1) ? fy : (1.f - fy);
                int xc = min(max(xi, 0), BW - 1);
                int yc = min(max(yi, 0), BH - 1);
                sampw_s[qq][lane][c] = valid ? (wt * bwx * bwy) : 0.f;
                sampi_s[qq][lane][c] = yc * BW + xc;
            }
        }
    }
    __syncthreads();

    // ---- Phase 4: gather, 16 LDGs in flight per query; write transposed ----
    // warp = one head (h = t>>5), lanes = hd dims -> each LDG is one full 128B line
    {
        const int h = t >> 5, d = t & 31;
        #pragma unroll 1
        for (int qq = 0; qq < QB; qq++) {
            const int flat = base + qq;
            const float* mb = memory + (size_t)(flat / NN) * (size_t)(HW*CC) + h*HD + d;

            float4 wv[4]; int4 iv[4];
            #pragma unroll
            for (int u = 0; u < 4; u++) {
                wv[u] = *(const float4*)&sampw_s[qq][h*4 + u][0];   // warp-uniform
                iv[u] = *(const int4*)&sampi_s[qq][h*4 + u][0];     // warp-uniform
            }
            float v[16];
            #pragma unroll
            for (int u = 0; u < 4; u++) {
                v[4*u+0] = mb[(size_t)iv[u].x * CC];
                v[4*u+1] = mb[(size_t)iv[u].y * CC];
                v[4*u+2] = mb[(size_t)iv[u].z * CC];
                v[4*u+3] = mb[(size_t)iv[u].w * CC];
            }
            float a0 = 0.f, a1 = 0.f;
            #pragma unroll
            for (int u = 0; u < 4; u++) {
                a0 += wv[u].x * v[4*u+0];
                a1 += wv[u].y * v[4*u+1];
                a0 += wv[u].z * v[4*u+2];
                a1 += wv[u].w * v[4*u+3];
            }
            bufT[h*HD + d][qq] = a0 + a1;   // fusedT[k][q]
        }
    }
    __syncthreads();

    // ---- Phase 5: output projection, packed f32x2, 4-deep w prefetch ----
    {
        unsigned long long acc[8];
        #pragma unroll
        for (int u = 0; u < 8; u++) acc[u] = 0ull;

        float wc[4], wn[4];
        #pragma unroll
        for (int j = 0; j < 4; j++) wc[j] = w_out[(size_t)j*CC + t];

        #pragma unroll 1
        for (int kb = 0; kb < CC; kb += 4) {
            const bool more = (kb + 4) < CC;
            #pragma unroll
            for (int j = 0; j < 4; j++)
                wn[j] = more ? w_out[(size_t)(kb + 4 + j)*CC + t] : 0.f;
            #pragma unroll
            for (int j = 0; j < 4; j++) {
                unsigned long long ww = pk2(wc[j]);
                const unsigned long long* row =
                    (const unsigned long long*)&bufT[kb + j][0];
                #pragma unroll
                for (int u = 0; u < 8; u++) ffma2(acc[u], row[u], ww);
            }
            #pragma unroll
            for (int j = 0; j < 4; j++) wc[j] = wn[j];
        }

        const float bo = b_out[t];
        #pragma unroll
        for (int u = 0; u < 8; u++) {
            float lo, hi; unpk2(acc[u], lo, hi);
            out[(size_t)(base + 2*u + 0)*CC + t] = lo + bo;
            out[(size_t)(base + 2*u + 1)*CC + t] = hi + bo;
        }
    }
}

extern "C" void kernel_launch(void* const* d_in, const int* in_sizes, int n_in,
                              void* d_out, int out_size) {
    const float* query  = (const float*)d_in[0];
    const float* memory = (const float*)d_in[1];
    const float* refpts = (const float*)d_in[2];
    const float* w_off  = (const float*)d_in[3];
    const float* b_off  = (const float*)d_in[4];
    const float* w_wt   = (const float*)d_in[5];
    const float* b_wt   = (const float*)d_in[6];
    const float* w_out  = (const float*)d_in[7];
    const float* b_out  = (const float*)d_in[8];

    deform_fused_kernel<<<NBLK, 256>>>(query, memory, refpts,
                                       w_off, b_off, w_wt, b_wt,
                                       w_out, b_out, (float*)d_out);
}

// round 9
// speedup vs baseline: 1.4649x; 1.0625x over previous
#include <cuda_runtime.h>
#include <math.h>

// Problem constants (fixed by the reference)
#define BB 8
#define NN 900
#define CC 256
#define HEADS 8
#define PP 4
#define HD 32
#define BH 200
#define BW 200
#define HW (BH*BW)
#define RADIUS 0.2f
#define QB 8                  // queries per block
#define NBLK ((BB*NN)/QB)     // 900 -> ~6 blocks/SM resident (cap 8), phases decorrelate
#define TST 12                // bufT row stride (floats): 48B, 16B-aligned for LDS.128

__device__ __forceinline__ unsigned long long pk2(float x) {
    unsigned long long r;
    asm("mov.b64 %0, {%1, %1};" : "=l"(r) : "f"(x));
    return r;
}
__device__ __forceinline__ void ffma2(unsigned long long& acc,
                                      unsigned long long a,
                                      unsigned long long b) {
    asm("fma.rn.f32x2 %0, %1, %2, %0;" : "+l"(acc) : "l"(a), "l"(b));
}
__device__ __forceinline__ void unpk2(unsigned long long v, float& lo, float& hi) {
    asm("mov.b64 {%0, %1}, %2;" : "=f"(lo), "=f"(hi) : "l"(v));
}

__global__ __launch_bounds__(128, 8)
void deform_fused_kernel(
    const float* __restrict__ query,
    const float* __restrict__ memory,
    const float* __restrict__ refpts,
    const float* __restrict__ w_off,
    const float* __restrict__ b_off,
    const float* __restrict__ w_wt,
    const float* __restrict__ b_wt,
    const float* __restrict__ w_out,
    const float* __restrict__ b_out,
    float* __restrict__ out)
{
    // Transposed union buffer: phases 1-2 hold queryT[k][q]; phases 4-5 hold fusedT[k][q]
    __shared__ float bufT[CC][TST];              // 12 KB
    __shared__ float ow_s[96][9];                // 3.4 KB (odd stride -> conflict-free reads)
    __shared__ float ref_s[QB][2];
    __shared__ float sampw_s[QB][HEADS*PP][4];   // 4 KB (rows 16B-aligned)
    __shared__ int   sampi_s[QB][HEADS*PP][4];   // 4 KB
    // ~23.5 KB/block; 8 blocks/SM = 188 KB

    const int t = threadIdx.x;
    const int base = blockIdx.x * QB;

    // ---- Phase 1: stage QB query rows, transposed ----
    #pragma unroll
    for (int half = 0; half < 2; half++) {
        const int k = t + half*128;
        #pragma unroll
        for (int j = 0; j < QB; j++)
            bufT[k][j] = query[(size_t)(base + j)*CC + k];
    }
    __syncthreads();

    // ---- Phase 2: offset+weight GEMV (threads 0..95); warp 3 stages refpts ----
    if (t >= 96) {
        if (t < 96 + 2*QB) {
            const int qq = (t - 96) >> 1, c = (t - 96) & 1;
            ref_s[qq][c] = refpts[(size_t)(base + qq)*2 + c];
        }
    } else {
        const bool is_off = (t < 64);
        const float* W = is_off ? w_off : w_wt;
        const int col  = is_off ? t : (t - 64);
        const int ldw  = is_off ? 64 : 32;

        unsigned long long acc[4];
        #pragma unroll
        for (int u = 0; u < 4; u++) acc[u] = 0ull;

        float wc[4], wn[4];
        #pragma unroll
        for (int j = 0; j < 4; j++) wc[j] = W[j*ldw + col];

        #pragma unroll 1
        for (int kb = 0; kb < CC; kb += 4) {
            const bool more = (kb + 4) < CC;
            #pragma unroll
            for (int j = 0; j < 4; j++)
                wn[j] = more ? W[(kb + 4 + j)*ldw + col] : 0.f;
            #pragma unroll
            for (int j = 0; j < 4; j++) {
                const unsigned long long ww = pk2(wc[j]);
                ulonglong2 r0 = *(const ulonglong2*)&bufT[kb + j][0];  // q0..3
                ulonglong2 r1 = *(const ulonglong2*)&bufT[kb + j][4];  // q4..7
                ffma2(acc[0], r0.x, ww);
                ffma2(acc[1], r0.y, ww);
                ffma2(acc[2], r1.x, ww);
                ffma2(acc[3], r1.y, ww);
            }
            #pragma unroll
            for (int j = 0; j < 4; j++) wc[j] = wn[j];
        }
        #pragma unroll
        for (int u = 0; u < 4; u++) {
            float lo, hi; unpk2(acc[u], lo, hi);
            ow_s[t][2*u+0] = lo;
            ow_s[t][2*u+1] = hi;
        }
    }
    __syncthreads();

    // ---- Phase 3: bias, tanh, softmax(P), bilinear setup ----
    // 4 warps; warp w handles queries w and w+4; lane = h*P + p
    {
        const int lane = t & 31;
        #pragma unroll
        for (int rep = 0; rep < 2; rep++) {
            const int qq = (t >> 5) + rep*4;
            float rx = ref_s[qq][0];
            float ry = ref_s[qq][1];

            float lgx = ow_s[2*lane  ][qq] + b_off[2*lane  ];
            float lgy = ow_s[2*lane+1][qq] + b_off[2*lane+1];
            float ox = tanhf(lgx) * RADIUS;
            float oy = tanhf(lgy) * RADIUS;
            float x = (rx + ox) * (float)BW - 0.5f;
            float y = (ry + oy) * (float)BH - 0.5f;
            float x0f = floorf(x), y0f = floorf(y);
            int   x0 = (int)x0f,   y0 = (int)y0f;
            float fx = x - x0f,    fy = y - y0f;

            float lg = ow_s[64 + lane][qq] + b_wt[lane];
            float m = lg;
            m = fmaxf(m, __shfl_xor_sync(0xffffffffu, m, 1));
            m = fmaxf(m, __shfl_xor_sync(0xffffffffu, m, 2));
            float e = expf(lg - m);
            float s = e;
            s += __shfl_xor_sync(0xffffffffu, s, 1);
            s += __shfl_xor_sync(0xffffffffu, s, 2);
            float wt = e / s;

            #pragma unroll
            for (int c = 0; c < 4; c++) {
                int xi = x0 + (c & 1);
                int yi = y0 + (c >> 1);
                bool valid = (xi >= 0) & (xi < BW) & (yi >= 0) & (yi < BH);
                float bwx = (c & 1)  ? fx : (1.f - fx);
                float bwy = (c >> 1) ? fy : (1.f - fy);
                int xc = min(max(xi, 0), BW - 1);
                int yc = min(max(yi, 0), BH - 1);
                sampw_s[qq][lane][c] = valid ? (wt * bwx * bwy) : 0.f;
                sampi_s[qq][lane][c] = yc * BW + xc;
            }
        }
    }
    __syncthreads();

    // ---- Phase 4: gather, 16 LDGs in flight; warp = 2 heads; write transposed ----
    {
        const int w = t >> 5, d = t & 31;
        #pragma unroll 1
        for (int qq = 0; qq < QB; qq++) {
            const float* mbase = memory + (size_t)((base + qq) / NN) * (size_t)(HW*CC);
            #pragma unroll
            for (int hh = 0; hh < 2; hh++) {
                const int h = 2*w + hh;
                const float* mb = mbase + h*HD + d;

                float4 wv[4]; int4 iv[4];
                #pragma unroll
                for (int u = 0; u < 4; u++) {
                    wv[u] = *(const float4*)&sampw_s[qq][h*4 + u][0];   // warp-uniform
                    iv[u] = *(const int4*)&sampi_s[qq][h*4 + u][0];     // warp-uniform
                }
                float v[16];
                #pragma unroll
                for (int u = 0; u < 4; u++) {
                    v[4*u+0] = mb[(size_t)iv[u].x * CC];
                    v[4*u+1] = mb[(size_t)iv[u].y * CC];
                    v[4*u+2] = mb[(size_t)iv[u].z * CC];
                    v[4*u+3] = mb[(size_t)iv[u].w * CC];
                }
                float a0 = 0.f, a1 = 0.f;
                #pragma unroll
                for (int u = 0; u < 4; u++) {
                    a0 += wv[u].x * v[4*u+0];
                    a1 += wv[u].y * v[4*u+1];
                    a0 += wv[u].z * v[4*u+2];
                    a1 += wv[u].w * v[4*u+3];
                }
                bufT[h*HD + d][qq] = a0 + a1;   // fusedT[k][q]
            }
        }
    }
    __syncthreads();

    // ---- Phase 5: output projection; thread handles cols t and t+128 ----
    {
        unsigned long long acc[8];
        #pragma unroll
        for (int u = 0; u < 8; u++) acc[u] = 0ull;

        float wc0[4], wc1[4], wn0[4], wn1[4];
        #pragma unroll
        for (int j = 0; j < 4; j++) {
            wc0[j] = w_out[(size_t)j*CC + t];
            wc1[j] = w_out[(size_t)j*CC + t + 128];
        }

        #pragma unroll 1
        for (int kb = 0; kb < CC; kb += 4) {
            const bool more = (kb + 4) < CC;
            #pragma unroll
            for (int j = 0; j < 4; j++) {
                wn0[j] = more ? w_out[(size_t)(kb + 4 + j)*CC + t]       : 0.f;
                wn1[j] = more ? w_out[(size_t)(kb + 4 + j)*CC + t + 128] : 0.f;
            }
            #pragma unroll
            for (int j = 0; j < 4; j++) {
                const int k = kb + j;
                ulonglong2 r0 = *(const ulonglong2*)&bufT[k][0];  // q0..3
                ulonglong2 r1 = *(const ulonglong2*)&bufT[k][4];  // q4..7
                const unsigned long long w0 = pk2(wc0[j]);
                const unsigned long long w1 = pk2(wc1[j]);
                ffma2(acc[0], r0.x, w0);
                ffma2(acc[1], r0.y, w0);
                ffma2(acc[2], r1.x, w0);
                ffma2(acc[3], r1.y, w0);
                ffma2(acc[4], r0.x, w1);
                ffma2(acc[5], r0.y, w1);
                ffma2(acc[6], r1.x, w1);
                ffma2(acc[7], r1.y, w1);
            }
            #pragma unroll
            for (int j = 0; j < 4; j++) { wc0[j] = wn0[j]; wc1[j] = wn1[j]; }
        }

        const float bo0 = b_out[t];
        const float bo1 = b_out[t + 128];
        #pragma unroll
        for (int u = 0; u < 4; u++) {
            float lo, hi;
            unpk2(acc[u], lo, hi);
            out[(size_t)(base + 2*u + 0)*CC + t] = lo + bo0;
            out[(size_t)(base + 2*u + 1)*CC + t] = hi + bo0;
            unpk2(acc[4+u], lo, hi);
            out[(size_t)(base + 2*u + 0)*CC + t + 128] = lo + bo1;
            out[(size_t)(base + 2*u + 1)*CC + t + 128] = hi + bo1;
        }
    }
}

extern "C" void kernel_launch(void* const* d_in, const int* in_sizes, int n_in,
                              void* d_out, int out_size) {
    const float* query  = (const float*)d_in[0];
    const float* memory = (const float*)d_in[1];
    const float* refpts = (const float*)d_in[2];
    const float* w_off  = (const float*)d_in[3];
    const float* b_off  = (const float*)d_in[4];
    const float* w_wt   = (const float*)d_in[5];
    const float* b_wt   = (const float*)d_in[6];
    const float* w_out  = (const float*)d_in[7];
    const float* b_out  = (const float*)d_in[8];

    deform_fused_kernel<<<NBLK, 128>>>(query, memory, refpts,
                                       w_off, b_off, w_wt, b_wt,
                                       w_out, b_out, (float*)d_out);
}